// round 11
// baseline (speedup 1.0000x reference)
#include <cuda_runtime.h>
#include <cuda_bf16.h>
#include <cstdint>

// out = X @ W_eff^T + bias, W_eff = W + 2*B@A
// Single-pass TF32 GEMM via mma.sync.m16n8k8 (base sm_103 target).
// R10: warp tile 64x64 (4x MMAs per LDSM byte), CTA 128x256, 8 warps,
// BK=64, 2-stage 96KB pipeline. A fed raw fp32 (HW RZ->tf32); systematic
// truncation scale cancelled via TRUNC_COMP folded into W_eff pre-round.

#define M_TOTAL 16384
#define N_DIM   1024
#define K_DIM   1024
#define R_RANK  16

#define BM 128
#define BN 256
#define BK 64
#define NCHUNK (K_DIM / BK)   // 16
#define KSTEPS (BK / 8)       // 8

// E[rel truncation loss] fp32->tf32 RZ, log-uniform mantissas: 2^-11*0.7213
#define TRUNC_COMP 1.000352f

// stage: X fp32 128x64 (32KB) + W tf32 256x64 (64KB); rows of 256B
#define STG_X 0
#define STG_W 32768
#define STAGE_BYTES 98304
#define NSTAGE 2
#define SMEM_BYTES (NSTAGE * STAGE_BYTES)   // 192KB

__device__ float g_Wtf[N_DIM * K_DIM];   // W_eff, compensated + tf32-rounded

// ---------------- PTX helpers ----------------
__device__ __forceinline__ uint32_t smem_u32(const void* p) {
    uint32_t a;
    asm("{ .reg .u64 t; cvta.to.shared.u64 t, %1; cvt.u32.u64 %0, t; }" : "=r"(a) : "l"(p));
    return a;
}

#define CP_ASYNC16(dst, src) \
    asm volatile("cp.async.cg.shared.global [%0], [%1], 16;" :: "r"(dst), "l"(src))
#define CP_COMMIT() asm volatile("cp.async.commit_group;" ::: "memory")
#define CP_WAIT1()  asm volatile("cp.async.wait_group 1;" ::: "memory")
#define CP_WAIT0()  asm volatile("cp.async.wait_group 0;" ::: "memory")

#define LDSM_X4(r0, r1, r2, r3, addr) \
    asm volatile("ldmatrix.sync.aligned.m8n8.x4.shared.b16 {%0,%1,%2,%3}, [%4];" \
                 : "=r"(r0), "=r"(r1), "=r"(r2), "=r"(r3) : "r"(addr))

#define MMA_TF32(d, a0, a1, a2, a3, b0, b1) \
    asm volatile("mma.sync.aligned.m16n8k8.row.col.f32.tf32.tf32.f32 " \
                 "{%0,%1,%2,%3}, {%4,%5,%6,%7}, {%8,%9}, {%0,%1,%2,%3};" \
                 : "+f"((d)[0]), "+f"((d)[1]), "+f"((d)[2]), "+f"((d)[3]) \
                 : "r"(a0), "r"(a1), "r"(a2), "r"(a3), "r"(b0), "r"(b1))

__device__ __forceinline__ uint32_t cvt_tf32(uint32_t x) {
    uint32_t r;
    asm("cvt.rna.tf32.f32 %0, %1;" : "=r"(r) : "r"(x));
    return r;
}

// ---------------------------------------------------------------------------
// Prep: W_eff = (W + 2*B@A) * TRUNC_COMP, rounded to tf32 (rna).
// ---------------------------------------------------------------------------
__global__ void build_weff_tf32_kernel(const float* __restrict__ W,
                                       const float* __restrict__ A,
                                       const float* __restrict__ Bm) {
    const int o = blockIdx.x;
    const int t = threadIdx.x;
    __shared__ float brow[R_RANK];
    if (t < R_RANK) brow[t] = 2.0f * Bm[o * R_RANK + t];
    __syncthreads();

    for (int k4 = t * 4; k4 < K_DIM; k4 += blockDim.x * 4) {
        float4 w = *(const float4*)&W[o * K_DIM + k4];
        float v[4] = {w.x, w.y, w.z, w.w};
        #pragma unroll
        for (int r = 0; r < R_RANK; r++) {
            float br = brow[r];
            const float4 a = *(const float4*)&A[r * K_DIM + k4];
            v[0] = fmaf(br, a.x, v[0]); v[1] = fmaf(br, a.y, v[1]);
            v[2] = fmaf(br, a.z, v[2]); v[3] = fmaf(br, a.w, v[3]);
        }
        uint4 o4;
        o4.x = cvt_tf32(__float_as_uint(v[0] * TRUNC_COMP));
        o4.y = cvt_tf32(__float_as_uint(v[1] * TRUNC_COMP));
        o4.z = cvt_tf32(__float_as_uint(v[2] * TRUNC_COMP));
        o4.w = cvt_tf32(__float_as_uint(v[3] * TRUNC_COMP));
        *(uint4*)&g_Wtf[o * K_DIM + k4] = o4;
    }
}

// ---------------------------------------------------------------------------
// Main GEMM: CTA 128x256, 256 threads (8 warps: 2M x 4N), warp tile 64x64.
// ---------------------------------------------------------------------------
__global__ __launch_bounds__(256) void lora_gemm_tf32_kernel(
    const float* __restrict__ X,
    const float* __restrict__ bias,
    float* __restrict__ Out) {
    extern __shared__ char smem[];
    const uint32_t sbase = smem_u32(smem);
    const int tid = threadIdx.x;
    const int lane = tid & 31;
    const int wid = tid >> 5;          // 0..7
    const int wm = wid & 1;            // 2 warps along M (64 rows each)
    const int wn = wid >> 1;           // 4 warps along N (64 cols each)

    const int block_m = blockIdx.y * BM;
    const int block_n = blockIdx.x * BN;

    // ---- cp.async: compact base+stride plan.
    // X: 2048 16B-chunks (8/thread), W: 4096 (16/thread). idx = tid + i*256:
    // row advances 16/i -> dst +4096B (swizzle invariant), src +16 rows.
    const int cr = tid >> 4;           // base row 0..15
    const int c16 = tid & 15;          // 16B chunk in 256B row
    const uint32_t dst_off = (uint32_t)(cr * 256 + ((c16 ^ (cr & 15)) << 4));
    const uint32_t dst_x = sbase + STG_X + dst_off;
    const uint32_t dst_w = sbase + STG_W + dst_off;
    const char* src_x = (const char*)(X + (size_t)(block_m + cr) * K_DIM + c16 * 4);
    const char* src_w = (const char*)(g_Wtf + (size_t)(block_n + cr) * K_DIM + c16 * 4);
    // per i: dst += 4096, src += 16 * 4096B; per chunk: src += BK*4 = 256B

    // ---- ldmatrix row/swizzle components ----
    const int arow_l = (lane & 7) + ((lane >> 3) & 1) * 8;  // row in 16-blk
    const int khalf  = (lane >> 4) & 1;                      // 16B chunk +0/+1

    float acc[4][8][4];
    #pragma unroll
    for (int mf = 0; mf < 4; mf++)
        #pragma unroll
        for (int nf = 0; nf < 8; nf++)
            #pragma unroll
            for (int r = 0; r < 4; r++)
                acc[mf][nf][r] = 0.0f;

    // prologue: stages 0, 1
    #pragma unroll
    for (int s = 0; s < 2; s++) {
        const uint32_t sb = (uint32_t)(s * STAGE_BYTES);
        const int ko = s * (BK * 4);
        #pragma unroll
        for (int i = 0; i < 8; i++)
            CP_ASYNC16(dst_x + sb + i * 4096, src_x + ko + i * (16 * K_DIM * 4));
        #pragma unroll
        for (int i = 0; i < 16; i++)
            CP_ASYNC16(dst_w + sb + i * 4096, src_w + ko + i * (16 * K_DIM * 4));
        CP_COMMIT();
    }

    for (int c = 0; c < NCHUNK; c++) {
        if (c + 1 < NCHUNK) CP_WAIT1(); else CP_WAIT0();
        __syncthreads();

        const uint32_t buf = sbase + (uint32_t)((c & 1) * STAGE_BYTES);

        #pragma unroll
        for (int ks = 0; ks < KSTEPS; ks++) {
            const int kchunk = ks * 2 + khalf;
            uint32_t a[4][4], b[4][4];
            // A: 4 m16-blocks of the 64-row warp tile (raw fp32 -> HW tf32)
            #pragma unroll
            for (int mf = 0; mf < 4; mf++) {
                const int row = wm * 64 + mf * 16 + arow_l;
                const uint32_t ao = buf + STG_X +
                    (uint32_t)(row * 256 + ((kchunk ^ (row & 15)) << 4));
                LDSM_X4(a[mf][0], a[mf][1], a[mf][2], a[mf][3], ao);
            }
            // B: 4 n16-blocks of the 64-col warp tile
            // regs: r0=(n+0,k0-3) r1=(n+8,k0-3) r2=(n+0,k4-7) r3=(n+8,k4-7)
            #pragma unroll
            for (int np = 0; np < 4; np++) {
                const int row = wn * 64 + np * 16 + arow_l;
                const uint32_t bo = buf + STG_W +
                    (uint32_t)(row * 256 + ((kchunk ^ (row & 15)) << 4));
                LDSM_X4(b[np][0], b[np][1], b[np][2], b[np][3], bo);
            }
            #pragma unroll
            for (int mf = 0; mf < 4; mf++)
                #pragma unroll
                for (int nf = 0; nf < 8; nf++) {
                    const int np = nf >> 1, h = nf & 1;
                    MMA_TF32(acc[mf][nf], a[mf][0], a[mf][1], a[mf][2], a[mf][3],
                             b[np][h], b[np][h + 2]);
                }
        }
        __syncthreads();   // all warps done reading buf before overwrite

        if (c + 2 < NCHUNK) {
            const uint32_t sb = (uint32_t)(((c + 2) & 1) * STAGE_BYTES);
            const int ko = (c + 2) * (BK * 4);
            #pragma unroll
            for (int i = 0; i < 8; i++)
                CP_ASYNC16(dst_x + sb + i * 4096, src_x + ko + i * (16 * K_DIM * 4));
            #pragma unroll
            for (int i = 0; i < 16; i++)
                CP_ASYNC16(dst_w + sb + i * 4096, src_w + ko + i * (16 * K_DIM * 4));
            CP_COMMIT();
        }
    }

    // ---- epilogue: bias + direct stores ----
    const int mbase = block_m + wm * 64 + (lane >> 2);
    const int ncol  = block_n + wn * 64 + 2 * (lane & 3);
    #pragma unroll
    for (int mf = 0; mf < 4; mf++) {
        const int r0 = mbase + mf * 16;
        #pragma unroll
        for (int nf = 0; nf < 8; nf++) {
            const int n = ncol + nf * 8;
            const float2 bv = *(const float2*)&bias[n];
            float2 o0 = make_float2(acc[mf][nf][0] + bv.x, acc[mf][nf][1] + bv.y);
            float2 o1 = make_float2(acc[mf][nf][2] + bv.x, acc[mf][nf][3] + bv.y);
            *(float2*)&Out[(size_t)r0 * N_DIM + n] = o0;
            *(float2*)&Out[(size_t)(r0 + 8) * N_DIM + n] = o1;
        }
    }
}

// ---------------------------------------------------------------------------
extern "C" void kernel_launch(void* const* d_in, const int* in_sizes, int n_in,
                              void* d_out, int out_size) {
    const float* x  = (const float*)d_in[0];
    const float* W  = (const float*)d_in[1];
    const float* b  = (const float*)d_in[2];
    const float* A  = (const float*)d_in[3];
    const float* Bm = (const float*)d_in[4];
    float* out = (float*)d_out;

    cudaFuncSetAttribute(lora_gemm_tf32_kernel,
                         cudaFuncAttributeMaxDynamicSharedMemorySize, SMEM_BYTES);

    build_weff_tf32_kernel<<<N_DIM, 256>>>(W, A, Bm);

    dim3 grid(N_DIM / BN, M_TOTAL / BM);   // (4, 128) = 512 CTAs
    lora_gemm_tf32_kernel<<<grid, 256, SMEM_BYTES>>>(x, b, out);
}

// round 12
// speedup vs baseline: 1.1114x; 1.1114x over previous
#include <cuda_runtime.h>
#include <cuda_fp16.h>
#include <cstdint>

// out = X @ W_eff^T + bias, W_eff = W + 2*B@A
// R12: 2-pass FP16 GEMM via mma.sync.m16n8k16 (k16 HMMA carries 2x MACs/instr
// vs tf32 k8; empirically higher per-instr issue rate).
//   x ~ xh (fp16 RN, err ~1.5e-4), w = wh + wl (fp16 split, err ~2^-21)
//   out = xh*wh + xh*wl + bias, fp32 accumulate. All cvt in prep kernels.

#define M_TOTAL 16384
#define N_DIM   1024
#define K_DIM   1024
#define R_RANK  16

#define BM 128
#define BN 128
#define BK 64
#define NCHUNK (K_DIM / BK)   // 16
#define KSTEPS (BK / 16)      // 4

// stage: Xh / Wh / Wl, each 128x64 fp16 = 16KB (128B rows)
#define STG_XH 0
#define STG_WH 16384
#define STG_WL 32768
#define STAGE_BYTES 49152
#define NSTAGE 3
#define SMEM_BYTES (NSTAGE * STAGE_BYTES)   // 144KB

__device__ __half g_Xh[M_TOTAL * K_DIM];
__device__ __half g_Wh[N_DIM * K_DIM];
__device__ __half g_Wl[N_DIM * K_DIM];

// ---------------- PTX helpers ----------------
__device__ __forceinline__ uint32_t smem_u32(const void* p) {
    uint32_t a;
    asm("{ .reg .u64 t; cvta.to.shared.u64 t, %1; cvt.u32.u64 %0, t; }" : "=r"(a) : "l"(p));
    return a;
}

#define CP_ASYNC16(dst, src) \
    asm volatile("cp.async.cg.shared.global [%0], [%1], 16;" :: "r"(dst), "l"(src))
#define CP_COMMIT() asm volatile("cp.async.commit_group;" ::: "memory")
#define CP_WAIT1()  asm volatile("cp.async.wait_group 1;" ::: "memory")
#define CP_WAIT0()  asm volatile("cp.async.wait_group 0;" ::: "memory")

#define LDSM_X4(r0, r1, r2, r3, addr) \
    asm volatile("ldmatrix.sync.aligned.m8n8.x4.shared.b16 {%0,%1,%2,%3}, [%4];" \
                 : "=r"(r0), "=r"(r1), "=r"(r2), "=r"(r3) : "r"(addr))

#define MMA_F16(d, a, b0, b1) \
    asm volatile("mma.sync.aligned.m16n8k16.row.col.f32.f16.f16.f32 " \
                 "{%0,%1,%2,%3}, {%4,%5,%6,%7}, {%8,%9}, {%0,%1,%2,%3};" \
                 : "+f"((d)[0]), "+f"((d)[1]), "+f"((d)[2]), "+f"((d)[3]) \
                 : "r"((a)[0]), "r"((a)[1]), "r"((a)[2]), "r"((a)[3]), \
                   "r"(b0), "r"(b1))

// pack fp16x2 {low=l, high=h}
__device__ __forceinline__ uint32_t pack_h2(float l, float h) {
    uint32_t r;
    asm("cvt.rn.f16x2.f32 %0, %1, %2;" : "=r"(r) : "f"(h), "f"(l));
    return r;
}

// ---------------------------------------------------------------------------
// Prep 1: W_eff = W + 2*B@A, split into fp16 hi + residual lo.
// ---------------------------------------------------------------------------
__global__ void build_weff_f16_kernel(const float* __restrict__ W,
                                      const float* __restrict__ A,
                                      const float* __restrict__ Bm) {
    const int o = blockIdx.x;
    const int t = threadIdx.x;
    __shared__ float brow[R_RANK];
    if (t < R_RANK) brow[t] = 2.0f * Bm[o * R_RANK + t];
    __syncthreads();

    for (int k4 = t * 4; k4 < K_DIM; k4 += blockDim.x * 4) {
        float4 w = *(const float4*)&W[o * K_DIM + k4];
        float v[4] = {w.x, w.y, w.z, w.w};
        #pragma unroll
        for (int r = 0; r < R_RANK; r++) {
            float br = brow[r];
            const float4 a = *(const float4*)&A[r * K_DIM + k4];
            v[0] = fmaf(br, a.x, v[0]); v[1] = fmaf(br, a.y, v[1]);
            v[2] = fmaf(br, a.z, v[2]); v[3] = fmaf(br, a.w, v[3]);
        }
        float h[4], l[4];
        #pragma unroll
        for (int i = 0; i < 4; i++) {
            h[i] = __half2float(__float2half_rn(v[i]));
            l[i] = v[i] - h[i];
        }
        *(uint2*)&g_Wh[o * K_DIM + k4] = make_uint2(pack_h2(h[0], h[1]), pack_h2(h[2], h[3]));
        *(uint2*)&g_Wl[o * K_DIM + k4] = make_uint2(pack_h2(l[0], l[1]), pack_h2(l[2], l[3]));
    }
}

// ---------------------------------------------------------------------------
// Prep 2: X fp32 -> fp16 (RN). 8 floats/thread.
// ---------------------------------------------------------------------------
__global__ __launch_bounds__(256) void cvt_x_f16_kernel(const float* __restrict__ X) {
    const size_t i8 = ((size_t)blockIdx.x * 256 + threadIdx.x) * 8;
    float4 v0 = *(const float4*)&X[i8];
    float4 v1 = *(const float4*)&X[i8 + 4];
    uint4 o;
    o.x = pack_h2(v0.x, v0.y);
    o.y = pack_h2(v0.z, v0.w);
    o.z = pack_h2(v1.x, v1.y);
    o.w = pack_h2(v1.z, v1.w);
    *(uint4*)&g_Xh[i8] = o;
}

// ---------------------------------------------------------------------------
// Main GEMM: 128x128 CTA, 512 threads (16 warps, 4M x 4N), warp tile 32x32,
// 2 HMMA passes (wh, wl) sharing the A fragment. 3-stage cp.async.
// ---------------------------------------------------------------------------
__global__ __launch_bounds__(512) void lora_gemm_f16_kernel(
    const float* __restrict__ bias,
    float* __restrict__ Out) {
    extern __shared__ char smem[];
    const uint32_t sbase = smem_u32(smem);
    const int tid = threadIdx.x;
    const int lane = tid & 31;
    const int wid = tid >> 5;          // 0..15
    const int wm = wid & 3;            // 4 warps along M (32 rows)
    const int wn = wid >> 2;           // 4 warps along N (32 cols)

    const int block_m = blockIdx.y * BM;
    const int block_n = blockIdx.x * BN;

    // ---- cp.async plan: 6 x 16B chunks/thread/stage (3 tiles x 1024) ----
    uint32_t cp_dst[6];
    const char* cp_src[6];
    #pragma unroll
    for (int i = 0; i < 6; i++) {
        int idx = tid + i * 512;           // 0..3071
        int tile = idx >> 10;              // 0:Xh 1:Wh 2:Wl
        int r   = (idx & 1023) >> 3;       // 0..127
        int c8  = idx & 7;                 // 16B chunk in 128B row
        uint32_t off = (uint32_t)(r * 128 + ((c8 ^ (r & 7)) << 4));
        const __half* g;
        int grow;
        if (tile == 0)      { g = g_Xh; grow = block_m + r; off += STG_XH; }
        else if (tile == 1) { g = g_Wh; grow = block_n + r; off += STG_WH; }
        else                { g = g_Wl; grow = block_n + r; off += STG_WL; }
        cp_src[i] = (const char*)(g + (size_t)grow * K_DIM + c8 * 8);
        cp_dst[i] = sbase + off;
    }
    // per chunk: src advances BK fp16 = 128B

    // ---- ldmatrix components (R3-verified layout) ----
    const int a_row = wm * 32 + (lane & 7) + ((lane >> 3) & 1) * 8;
    const uint32_t a_swz = (uint32_t)((a_row & 7) * 16);
    const int a_khalf = ((lane >> 4) & 1) * 16;
    const int b_row = wn * 32 + (lane & 7) + ((lane >> 4) & 1) * 8;
    const uint32_t b_swz = (uint32_t)((b_row & 7) * 16);
    const int b_khalf = ((lane >> 3) & 1) * 16;

    float acc[2][4][4];
    #pragma unroll
    for (int mf = 0; mf < 2; mf++)
        #pragma unroll
        for (int nf = 0; nf < 4; nf++)
            #pragma unroll
            for (int r = 0; r < 4; r++)
                acc[mf][nf][r] = 0.0f;

    // prologue: stages 0, 1
    #pragma unroll
    for (int i = 0; i < 6; i++) CP_ASYNC16(cp_dst[i], cp_src[i]);
    CP_COMMIT();
    #pragma unroll
    for (int i = 0; i < 6; i++) CP_ASYNC16(cp_dst[i] + STAGE_BYTES, cp_src[i] + BK * 2);
    CP_COMMIT();

    for (int c = 0; c < NCHUNK; c++) {
        if (c + 1 < NCHUNK) CP_WAIT1(); else CP_WAIT0();
        __syncthreads();

        if (c + 2 < NCHUNK) {
            const uint32_t stg = (uint32_t)(((c + 2) % NSTAGE) * STAGE_BYTES);
            #pragma unroll
            for (int i = 0; i < 6; i++)
                CP_ASYNC16(cp_dst[i] + stg, cp_src[i] + (c + 2) * BK * 2);
            CP_COMMIT();
        }

        const uint32_t buf = sbase + (uint32_t)((c % NSTAGE) * STAGE_BYTES);

        #pragma unroll
        for (int ks = 0; ks < KSTEPS; ks++) {
            uint32_t a[2][4], bh[4][2], bl[4][2];
            const uint32_t akb = (uint32_t)(ks * 32 + a_khalf) ^ a_swz;
            const uint32_t bkb = (uint32_t)(ks * 32 + b_khalf) ^ b_swz;
            // A fragments: 2 m16-blocks (shared by both B passes)
            #pragma unroll
            for (int mf = 0; mf < 2; mf++) {
                const uint32_t ao = (uint32_t)((a_row + mf * 16) * 128) + akb;
                LDSM_X4(a[mf][0], a[mf][1], a[mf][2], a[mf][3], buf + STG_XH + ao);
            }
            // B fragments: 2 n16-blocks each of Wh and Wl
            #pragma unroll
            for (int np = 0; np < 2; np++) {
                const uint32_t bo = (uint32_t)((b_row + np * 16) * 128) + bkb;
                LDSM_X4(bh[np * 2][0], bh[np * 2][1], bh[np * 2 + 1][0], bh[np * 2 + 1][1],
                        buf + STG_WH + bo);
                LDSM_X4(bl[np * 2][0], bl[np * 2][1], bl[np * 2 + 1][0], bl[np * 2 + 1][1],
                        buf + STG_WL + bo);
            }
            #pragma unroll
            for (int mf = 0; mf < 2; mf++)
                #pragma unroll
                for (int nf = 0; nf < 4; nf++) {
                    MMA_F16(acc[mf][nf], a[mf], bh[nf][0], bh[nf][1]);
                    MMA_F16(acc[mf][nf], a[mf], bl[nf][0], bl[nf][1]);
                }
        }
        // buffer reuse ordered by next iteration's wait + syncthreads
    }

    // ---- epilogue: bias + direct stores (R3-verified mapping) ----
    const int mrow = block_m + wm * 32 + (lane >> 2);
    const int ncol = block_n + wn * 32 + 2 * (lane & 3);
    #pragma unroll
    for (int mf = 0; mf < 2; mf++) {
        #pragma unroll
        for (int nf = 0; nf < 4; nf++) {
            const int n = ncol + nf * 8;
            const float2 bv = *(const float2*)&bias[n];
            const int r0 = mrow + mf * 16;
            float2 o0 = make_float2(acc[mf][nf][0] + bv.x, acc[mf][nf][1] + bv.y);
            float2 o1 = make_float2(acc[mf][nf][2] + bv.x, acc[mf][nf][3] + bv.y);
            *(float2*)&Out[(size_t)r0 * N_DIM + n] = o0;
            *(float2*)&Out[(size_t)(r0 + 8) * N_DIM + n] = o1;
        }
    }
}

// ---------------------------------------------------------------------------
extern "C" void kernel_launch(void* const* d_in, const int* in_sizes, int n_in,
                              void* d_out, int out_size) {
    const float* x  = (const float*)d_in[0];
    const float* W  = (const float*)d_in[1];
    const float* b  = (const float*)d_in[2];
    const float* A  = (const float*)d_in[3];
    const float* Bm = (const float*)d_in[4];
    float* out = (float*)d_out;

    cudaFuncSetAttribute(lora_gemm_f16_kernel,
                         cudaFuncAttributeMaxDynamicSharedMemorySize, SMEM_BYTES);

    build_weff_f16_kernel<<<N_DIM, 256>>>(W, A, Bm);
    cvt_x_f16_kernel<<<(M_TOTAL * K_DIM) / (256 * 8), 256>>>(x);

    dim3 grid(N_DIM / BN, M_TOTAL / BM);   // (8, 128)
    lora_gemm_f16_kernel<<<grid, 512, SMEM_BYTES>>>(b, out);
}

// round 13
// speedup vs baseline: 1.6855x; 1.5165x over previous
#include <cuda_runtime.h>
#include <cuda_fp16.h>
#include <cstdint>

// out = X @ W_eff^T + bias, W_eff = W + 2*B@A
// R13: SINGLE-pass FP16 GEMM via mma.sync.m16n8k16.
// fp16 mantissa (10 bits) == tf32 mantissa; single-pass tf32 measured
// rel_err 2.9e-4 -> single-pass fp16 lands the same, under the 1e-3 budget,
// at HALF of R12's HMMA instruction count (the measured rate limiter).

#define M_TOTAL 16384
#define N_DIM   1024
#define K_DIM   1024
#define R_RANK  16

#define BM 128
#define BN 128
#define BK 64
#define NCHUNK (K_DIM / BK)   // 16
#define KSTEPS (BK / 16)      // 4

// stage: Xh / Wh, each 128x64 fp16 = 16KB (128B rows)
#define STG_XH 0
#define STG_WH 16384
#define STAGE_BYTES 32768
#define NSTAGE 3
#define SMEM_BYTES (NSTAGE * STAGE_BYTES)   // 96KB

__device__ __half g_Xh[M_TOTAL * K_DIM];
__device__ __half g_Wh[N_DIM * K_DIM];

// ---------------- PTX helpers ----------------
__device__ __forceinline__ uint32_t smem_u32(const void* p) {
    uint32_t a;
    asm("{ .reg .u64 t; cvta.to.shared.u64 t, %1; cvt.u32.u64 %0, t; }" : "=r"(a) : "l"(p));
    return a;
}

#define CP_ASYNC16(dst, src) \
    asm volatile("cp.async.cg.shared.global [%0], [%1], 16;" :: "r"(dst), "l"(src))
#define CP_COMMIT() asm volatile("cp.async.commit_group;" ::: "memory")
#define CP_WAIT1()  asm volatile("cp.async.wait_group 1;" ::: "memory")
#define CP_WAIT0()  asm volatile("cp.async.wait_group 0;" ::: "memory")

#define LDSM_X4(r0, r1, r2, r3, addr) \
    asm volatile("ldmatrix.sync.aligned.m8n8.x4.shared.b16 {%0,%1,%2,%3}, [%4];" \
                 : "=r"(r0), "=r"(r1), "=r"(r2), "=r"(r3) : "r"(addr))

#define MMA_F16(d, a, b0, b1) \
    asm volatile("mma.sync.aligned.m16n8k16.row.col.f32.f16.f16.f32 " \
                 "{%0,%1,%2,%3}, {%4,%5,%6,%7}, {%8,%9}, {%0,%1,%2,%3};" \
                 : "+f"((d)[0]), "+f"((d)[1]), "+f"((d)[2]), "+f"((d)[3]) \
                 : "r"((a)[0]), "r"((a)[1]), "r"((a)[2]), "r"((a)[3]), \
                   "r"(b0), "r"(b1))

// pack fp16x2 {low=l, high=h}
__device__ __forceinline__ uint32_t pack_h2(float l, float h) {
    uint32_t r;
    asm("cvt.rn.f16x2.f32 %0, %1, %2;" : "=r"(r) : "f"(h), "f"(l));
    return r;
}

// ---------------------------------------------------------------------------
// Prep 1: W_eff = W + 2*B@A, fp16 (RN).
// ---------------------------------------------------------------------------
__global__ void build_weff_f16_kernel(const float* __restrict__ W,
                                      const float* __restrict__ A,
                                      const float* __restrict__ Bm) {
    const int o = blockIdx.x;
    const int t = threadIdx.x;
    __shared__ float brow[R_RANK];
    if (t < R_RANK) brow[t] = 2.0f * Bm[o * R_RANK + t];
    __syncthreads();

    for (int k4 = t * 4; k4 < K_DIM; k4 += blockDim.x * 4) {
        float4 w = *(const float4*)&W[o * K_DIM + k4];
        float v[4] = {w.x, w.y, w.z, w.w};
        #pragma unroll
        for (int r = 0; r < R_RANK; r++) {
            float br = brow[r];
            const float4 a = *(const float4*)&A[r * K_DIM + k4];
            v[0] = fmaf(br, a.x, v[0]); v[1] = fmaf(br, a.y, v[1]);
            v[2] = fmaf(br, a.z, v[2]); v[3] = fmaf(br, a.w, v[3]);
        }
        *(uint2*)&g_Wh[o * K_DIM + k4] =
            make_uint2(pack_h2(v[0], v[1]), pack_h2(v[2], v[3]));
    }
}

// ---------------------------------------------------------------------------
// Prep 2: X fp32 -> fp16 (RN). 8 floats/thread.
// ---------------------------------------------------------------------------
__global__ __launch_bounds__(256) void cvt_x_f16_kernel(const float* __restrict__ X) {
    const size_t i8 = ((size_t)blockIdx.x * 256 + threadIdx.x) * 8;
    float4 v0 = *(const float4*)&X[i8];
    float4 v1 = *(const float4*)&X[i8 + 4];
    uint4 o;
    o.x = pack_h2(v0.x, v0.y);
    o.y = pack_h2(v0.z, v0.w);
    o.z = pack_h2(v1.x, v1.y);
    o.w = pack_h2(v1.z, v1.w);
    *(uint4*)&g_Xh[i8] = o;
}

// ---------------------------------------------------------------------------
// Main GEMM: 128x128 CTA, 512 threads (16 warps, 4M x 4N), warp tile 32x32,
// single HMMA pass. 3-stage cp.async.
// ---------------------------------------------------------------------------
__global__ __launch_bounds__(512) void lora_gemm_f16_kernel(
    const float* __restrict__ bias,
    float* __restrict__ Out) {
    extern __shared__ char smem[];
    const uint32_t sbase = smem_u32(smem);
    const int tid = threadIdx.x;
    const int lane = tid & 31;
    const int wid = tid >> 5;          // 0..15
    const int wm = wid & 3;            // 4 warps along M (32 rows)
    const int wn = wid >> 2;           // 4 warps along N (32 cols)

    const int block_m = blockIdx.y * BM;
    const int block_n = blockIdx.x * BN;

    // ---- cp.async plan: 4 x 16B chunks/thread/stage (2 tiles x 1024) ----
    uint32_t cp_dst[4];
    const char* cp_src[4];
    #pragma unroll
    for (int i = 0; i < 4; i++) {
        int idx = tid + i * 512;           // 0..2047
        int tile = idx >> 10;              // 0:Xh 1:Wh
        int r   = (idx & 1023) >> 3;       // 0..127
        int c8  = idx & 7;                 // 16B chunk in 128B row
        uint32_t off = (uint32_t)(r * 128 + ((c8 ^ (r & 7)) << 4));
        const __half* g;
        int grow;
        if (tile == 0) { g = g_Xh; grow = block_m + r; off += STG_XH; }
        else           { g = g_Wh; grow = block_n + r; off += STG_WH; }
        cp_src[i] = (const char*)(g + (size_t)grow * K_DIM + c8 * 8);
        cp_dst[i] = sbase + off;
    }
    // per chunk: src advances BK fp16 = 128B

    // ---- ldmatrix components (R3/R12-verified layout) ----
    const int a_row = wm * 32 + (lane & 7) + ((lane >> 3) & 1) * 8;
    const uint32_t a_swz = (uint32_t)((a_row & 7) * 16);
    const int a_khalf = ((lane >> 4) & 1) * 16;
    const int b_row = wn * 32 + (lane & 7) + ((lane >> 4) & 1) * 8;
    const uint32_t b_swz = (uint32_t)((b_row & 7) * 16);
    const int b_khalf = ((lane >> 3) & 1) * 16;

    float acc[2][4][4];
    #pragma unroll
    for (int mf = 0; mf < 2; mf++)
        #pragma unroll
        for (int nf = 0; nf < 4; nf++)
            #pragma unroll
            for (int r = 0; r < 4; r++)
                acc[mf][nf][r] = 0.0f;

    // prologue: stages 0, 1
    #pragma unroll
    for (int i = 0; i < 4; i++) CP_ASYNC16(cp_dst[i], cp_src[i]);
    CP_COMMIT();
    #pragma unroll
    for (int i = 0; i < 4; i++) CP_ASYNC16(cp_dst[i] + STAGE_BYTES, cp_src[i] + BK * 2);
    CP_COMMIT();

    for (int c = 0; c < NCHUNK; c++) {
        if (c + 1 < NCHUNK) CP_WAIT1(); else CP_WAIT0();
        __syncthreads();

        if (c + 2 < NCHUNK) {
            const uint32_t stg = (uint32_t)(((c + 2) % NSTAGE) * STAGE_BYTES);
            #pragma unroll
            for (int i = 0; i < 4; i++)
                CP_ASYNC16(cp_dst[i] + stg, cp_src[i] + (c + 2) * BK * 2);
            CP_COMMIT();
        }

        const uint32_t buf = sbase + (uint32_t)((c % NSTAGE) * STAGE_BYTES);

        #pragma unroll
        for (int ks = 0; ks < KSTEPS; ks++) {
            uint32_t a[2][4], bh[4][2];
            const uint32_t akb = (uint32_t)(ks * 32 + a_khalf) ^ a_swz;
            const uint32_t bkb = (uint32_t)(ks * 32 + b_khalf) ^ b_swz;
            #pragma unroll
            for (int mf = 0; mf < 2; mf++) {
                const uint32_t ao = (uint32_t)((a_row + mf * 16) * 128) + akb;
                LDSM_X4(a[mf][0], a[mf][1], a[mf][2], a[mf][3], buf + STG_XH + ao);
            }
            #pragma unroll
            for (int np = 0; np < 2; np++) {
                const uint32_t bo = (uint32_t)((b_row + np * 16) * 128) + bkb;
                LDSM_X4(bh[np * 2][0], bh[np * 2][1], bh[np * 2 + 1][0], bh[np * 2 + 1][1],
                        buf + STG_WH + bo);
            }
            #pragma unroll
            for (int mf = 0; mf < 2; mf++)
                #pragma unroll
                for (int nf = 0; nf < 4; nf++)
                    MMA_F16(acc[mf][nf], a[mf], bh[nf][0], bh[nf][1]);
        }
        // buffer reuse ordered by next iteration's wait + syncthreads
    }

    // ---- epilogue: bias + direct stores ----
    const int mrow = block_m + wm * 32 + (lane >> 2);
    const int ncol = block_n + wn * 32 + 2 * (lane & 3);
    #pragma unroll
    for (int mf = 0; mf < 2; mf++) {
        #pragma unroll
        for (int nf = 0; nf < 4; nf++) {
            const int n = ncol + nf * 8;
            const float2 bv = *(const float2*)&bias[n];
            const int r0 = mrow + mf * 16;
            float2 o0 = make_float2(acc[mf][nf][0] + bv.x, acc[mf][nf][1] + bv.y);
            float2 o1 = make_float2(acc[mf][nf][2] + bv.x, acc[mf][nf][3] + bv.y);
            *(float2*)&Out[(size_t)r0 * N_DIM + n] = o0;
            *(float2*)&Out[(size_t)(r0 + 8) * N_DIM + n] = o1;
        }
    }
}

// ---------------------------------------------------------------------------
extern "C" void kernel_launch(void* const* d_in, const int* in_sizes, int n_in,
                              void* d_out, int out_size) {
    const float* x  = (const float*)d_in[0];
    const float* W  = (const float*)d_in[1];
    const float* b  = (const float*)d_in[2];
    const float* A  = (const float*)d_in[3];
    const float* Bm = (const float*)d_in[4];
    float* out = (float*)d_out;

    cudaFuncSetAttribute(lora_gemm_f16_kernel,
                         cudaFuncAttributeMaxDynamicSharedMemorySize, SMEM_BYTES);

    build_weff_f16_kernel<<<N_DIM, 256>>>(W, A, Bm);
    cvt_x_f16_kernel<<<(M_TOTAL * K_DIM) / (256 * 8), 256>>>(x);

    dim3 grid(N_DIM / BN, M_TOTAL / BM);   // (8, 128)
    lora_gemm_f16_kernel<<<grid, 512, SMEM_BYTES>>>(b, out);
}

// round 16
// speedup vs baseline: 2.1177x; 1.2565x over previous
#include <cuda_runtime.h>
#include <cuda_fp16.h>
#include <cstdint>

// out = X @ W_eff^T + bias, W_eff = W + 2*B@A
// R16 = R14 with the B-fragment register-order bug fixed:
// ldmatrix.x4 with k-half on lane bit3, row+8 on lane bit4 yields
//   r0=(n0-7,k0-7) r1=(n0-7,k8-15) r2=(n8-15,k0-7) r3=(n8-15,k8-15)
// so the MMA for nf=np*2+h must consume (b[np][2h], b[np][2h+1]).
// Single-pass FP16 k16 GEMM. CTA 128x128, 8 warps (4M x 2N), warp tile
// 32x64, 3-stage 32KB, 2 CTAs/SM. Fused prep kernel (X cvt + W_eff build).

#define M_TOTAL 16384
#define N_DIM   1024
#define K_DIM   1024
#define R_RANK  16

#define BM 128
#define BN 128
#define BK 64
#define NCHUNK (K_DIM / BK)   // 16
#define KSTEPS (BK / 16)      // 4

// stage: Xh / Wh, each 128x64 fp16 = 16KB (128B rows)
#define STG_XH 0
#define STG_WH 16384
#define STAGE_BYTES 32768
#define NSTAGE 3
#define SMEM_BYTES (NSTAGE * STAGE_BYTES)   // 96KB -> 2 CTAs/SM

#define XBLOCKS ((M_TOTAL * K_DIM) / (256 * 8))   // 8192

__device__ __half g_Xh[M_TOTAL * K_DIM];
__device__ __half g_Wh[N_DIM * K_DIM];

// ---------------- PTX helpers ----------------
__device__ __forceinline__ uint32_t smem_u32(const void* p) {
    uint32_t a;
    asm("{ .reg .u64 t; cvta.to.shared.u64 t, %1; cvt.u32.u64 %0, t; }" : "=r"(a) : "l"(p));
    return a;
}

#define CP_ASYNC16(dst, src) \
    asm volatile("cp.async.cg.shared.global [%0], [%1], 16;" :: "r"(dst), "l"(src))
#define CP_COMMIT() asm volatile("cp.async.commit_group;" ::: "memory")
#define CP_WAIT1()  asm volatile("cp.async.wait_group 1;" ::: "memory")
#define CP_WAIT0()  asm volatile("cp.async.wait_group 0;" ::: "memory")

#define LDSM_X4(r0, r1, r2, r3, addr) \
    asm volatile("ldmatrix.sync.aligned.m8n8.x4.shared.b16 {%0,%1,%2,%3}, [%4];" \
                 : "=r"(r0), "=r"(r1), "=r"(r2), "=r"(r3) : "r"(addr))

#define MMA_F16(d, a, b0, b1) \
    asm volatile("mma.sync.aligned.m16n8k16.row.col.f32.f16.f16.f32 " \
                 "{%0,%1,%2,%3}, {%4,%5,%6,%7}, {%8,%9}, {%0,%1,%2,%3};" \
                 : "+f"((d)[0]), "+f"((d)[1]), "+f"((d)[2]), "+f"((d)[3]) \
                 : "r"((a)[0]), "r"((a)[1]), "r"((a)[2]), "r"((a)[3]), \
                   "r"(b0), "r"(b1))

// pack fp16x2 {low=l, high=h}
__device__ __forceinline__ uint32_t pack_h2(float l, float h) {
    uint32_t r;
    asm("cvt.rn.f16x2.f32 %0, %1, %2;" : "=r"(r) : "f"(h), "f"(l));
    return r;
}

// ---------------------------------------------------------------------------
// Fused prep: blocks [0, XBLOCKS) convert X fp32->fp16;
//             blocks [XBLOCKS, XBLOCKS+N_DIM) build one W_eff row each.
// ---------------------------------------------------------------------------
__global__ __launch_bounds__(256) void prep_kernel(const float* __restrict__ X,
                                                   const float* __restrict__ W,
                                                   const float* __restrict__ A,
                                                   const float* __restrict__ Bm) {
    __shared__ float brow[R_RANK];
    const int t = threadIdx.x;

    if (blockIdx.x < XBLOCKS) {
        const size_t i8 = ((size_t)blockIdx.x * 256 + t) * 8;
        float4 v0 = *(const float4*)&X[i8];
        float4 v1 = *(const float4*)&X[i8 + 4];
        uint4 o;
        o.x = pack_h2(v0.x, v0.y);
        o.y = pack_h2(v0.z, v0.w);
        o.z = pack_h2(v1.x, v1.y);
        o.w = pack_h2(v1.z, v1.w);
        *(uint4*)&g_Xh[i8] = o;
    } else {
        const int o = blockIdx.x - XBLOCKS;
        if (t < R_RANK) brow[t] = 2.0f * Bm[o * R_RANK + t];
        __syncthreads();

        for (int k4 = t * 4; k4 < K_DIM; k4 += 256 * 4) {
            float4 w = *(const float4*)&W[o * K_DIM + k4];
            float v[4] = {w.x, w.y, w.z, w.w};
            #pragma unroll
            for (int r = 0; r < R_RANK; r++) {
                float br = brow[r];
                const float4 a = *(const float4*)&A[r * K_DIM + k4];
                v[0] = fmaf(br, a.x, v[0]); v[1] = fmaf(br, a.y, v[1]);
                v[2] = fmaf(br, a.z, v[2]); v[3] = fmaf(br, a.w, v[3]);
            }
            *(uint2*)&g_Wh[o * K_DIM + k4] =
                make_uint2(pack_h2(v[0], v[1]), pack_h2(v[2], v[3]));
        }
    }
}

// ---------------------------------------------------------------------------
// Main GEMM: 128x128 CTA, 256 threads (8 warps: 4M x 2N), warp tile 32x64.
// ---------------------------------------------------------------------------
__global__ __launch_bounds__(256, 2) void lora_gemm_f16_kernel(
    const float* __restrict__ bias,
    float* __restrict__ Out) {
    extern __shared__ char smem[];
    const uint32_t sbase = smem_u32(smem);
    const int tid = threadIdx.x;
    const int lane = tid & 31;
    const int wid = tid >> 5;          // 0..7
    const int wm = wid & 3;            // 4 warps along M (32 rows each)
    const int wn = wid >> 2;           // 2 warps along N (64 cols each)

    const int block_m = blockIdx.y * BM;
    const int block_n = blockIdx.x * BN;

    // ---- cp.async: compact base+stride plan. 2048 chunks, 8/thread.
    // cr = base row 0..31; i advances rows by 32 (swizzle-invariant: row&7 same)
    const int cr = tid >> 3;           // 0..31
    const int c8 = tid & 7;            // 16B chunk in 128B row
    const uint32_t dst_off = (uint32_t)(cr * 128 + ((c8 ^ (cr & 7)) << 4));
    const uint32_t dst_x = sbase + STG_XH + dst_off;
    const uint32_t dst_w = sbase + STG_WH + dst_off;
    const char* src_x = (const char*)(g_Xh + (size_t)(block_m + cr) * K_DIM + c8 * 8);
    const char* src_w = (const char*)(g_Wh + (size_t)(block_n + cr) * K_DIM + c8 * 8);
    // per i: dst += 32*128 = 4096B, src += 32 rows = 32*K_DIM*2 B
    // per chunk: src += BK*2 = 128B

    // ---- ldmatrix components ----
    const int a_row = wm * 32 + (lane & 7) + ((lane >> 3) & 1) * 8;
    const uint32_t a_swz = (uint32_t)((a_row & 7) * 16);
    const int a_khalf = ((lane >> 4) & 1) * 16;
    const int b_rowl = (lane & 7) + ((lane >> 4) & 1) * 8;   // + wn*64 + np*16
    const int b_khalf = ((lane >> 3) & 1) * 16;

    float acc[2][8][4];
    #pragma unroll
    for (int mf = 0; mf < 2; mf++)
        #pragma unroll
        for (int nf = 0; nf < 8; nf++)
            #pragma unroll
            for (int r = 0; r < 4; r++)
                acc[mf][nf][r] = 0.0f;

    // prologue: stages 0, 1
    #pragma unroll
    for (int s = 0; s < 2; s++) {
        const uint32_t sb = (uint32_t)(s * STAGE_BYTES);
        const int ko = s * (BK * 2);
        #pragma unroll
        for (int i = 0; i < 4; i++) {
            CP_ASYNC16(dst_x + sb + i * 4096, src_x + ko + i * (32 * K_DIM * 2));
            CP_ASYNC16(dst_w + sb + i * 4096, src_w + ko + i * (32 * K_DIM * 2));
        }
        CP_COMMIT();
    }

    for (int c = 0; c < NCHUNK; c++) {
        if (c + 1 < NCHUNK) CP_WAIT1(); else CP_WAIT0();
        __syncthreads();

        if (c + 2 < NCHUNK) {
            const uint32_t sb = (uint32_t)(((c + 2) % NSTAGE) * STAGE_BYTES);
            const int ko = (c + 2) * (BK * 2);
            #pragma unroll
            for (int i = 0; i < 4; i++) {
                CP_ASYNC16(dst_x + sb + i * 4096, src_x + ko + i * (32 * K_DIM * 2));
                CP_ASYNC16(dst_w + sb + i * 4096, src_w + ko + i * (32 * K_DIM * 2));
            }
            CP_COMMIT();
        }

        const uint32_t buf = sbase + (uint32_t)((c % NSTAGE) * STAGE_BYTES);

        #pragma unroll
        for (int ks = 0; ks < KSTEPS; ks++) {
            uint32_t a[2][4], b[4][4];
            const uint32_t akb = (uint32_t)(ks * 32 + a_khalf) ^ a_swz;
            const uint32_t bkb = (uint32_t)(ks * 32 + b_khalf);
            // A: 2 m16-blocks of the 32-row warp tile
            #pragma unroll
            for (int mf = 0; mf < 2; mf++) {
                const uint32_t ao = (uint32_t)((a_row + mf * 16) * 128) + akb;
                LDSM_X4(a[mf][0], a[mf][1], a[mf][2], a[mf][3], buf + STG_XH + ao);
            }
            // B: 4 n16-blocks of the 64-col warp tile.
            // regs: r0=(n0-7,k0-7) r1=(n0-7,k8-15) r2=(n8-15,k0-7) r3=(n8-15,k8-15)
            #pragma unroll
            for (int np = 0; np < 4; np++) {
                const int row = wn * 64 + np * 16 + b_rowl;
                const uint32_t bo = (uint32_t)(row * 128) +
                                    (bkb ^ (uint32_t)((row & 7) * 16));
                LDSM_X4(b[np][0], b[np][1], b[np][2], b[np][3], buf + STG_WH + bo);
            }
            #pragma unroll
            for (int mf = 0; mf < 2; mf++)
                #pragma unroll
                for (int nf = 0; nf < 8; nf++) {
                    const int np = nf >> 1, h = nf & 1;
                    // nf = np*2+h -> n-block (np*16 + h*8), pair (b[np][2h], b[np][2h+1])
                    MMA_F16(acc[mf][nf], a[mf], b[np][2 * h], b[np][2 * h + 1]);
                }
        }
        // buffer reuse ordered by next iteration's wait + syncthreads
    }

    // ---- epilogue: bias + direct stores ----
    const int mrow = block_m + wm * 32 + (lane >> 2);
    const int ncol = block_n + wn * 64 + 2 * (lane & 3);
    #pragma unroll
    for (int mf = 0; mf < 2; mf++) {
        const int r0 = mrow + mf * 16;
        #pragma unroll
        for (int nf = 0; nf < 8; nf++) {
            const int n = ncol + nf * 8;
            const float2 bv = *(const float2*)&bias[n];
            float2 o0 = make_float2(acc[mf][nf][0] + bv.x, acc[mf][nf][1] + bv.y);
            float2 o1 = make_float2(acc[mf][nf][2] + bv.x, acc[mf][nf][3] + bv.y);
            *(float2*)&Out[(size_t)r0 * N_DIM + n] = o0;
            *(float2*)&Out[(size_t)(r0 + 8) * N_DIM + n] = o1;
        }
    }
}

// ---------------------------------------------------------------------------
extern "C" void kernel_launch(void* const* d_in, const int* in_sizes, int n_in,
                              void* d_out, int out_size) {
    const float* x  = (const float*)d_in[0];
    const float* W  = (const float*)d_in[1];
    const float* b  = (const float*)d_in[2];
    const float* A  = (const float*)d_in[3];
    const float* Bm = (const float*)d_in[4];
    float* out = (float*)d_out;

    cudaFuncSetAttribute(lora_gemm_f16_kernel,
                         cudaFuncAttributeMaxDynamicSharedMemorySize, SMEM_BYTES);

    prep_kernel<<<XBLOCKS + N_DIM, 256>>>(x, W, A, Bm);

    dim3 grid(N_DIM / BN, M_TOTAL / BM);   // (8, 128)
    lora_gemm_f16_kernel<<<grid, 256, SMEM_BYTES>>>(b, out);
}

// round 17
// speedup vs baseline: 2.1507x; 1.0156x over previous
#include <cuda_runtime.h>
#include <cuda_fp16.h>
#include <cstdint>

// out = X @ W_eff^T + bias, W_eff = W + 2*B@A
// R17: single-pass FP16 k16 GEMM. CTA 64x128 (grid 2048, finer drain
// granularity), 8 warps (2M x 4N) of 32x32, acc=32 -> ~80 regs ->
// 3 CTAs/SM (24 warps/SM), 3-stage 24KB pipeline. Fused prep kernel.

#define M_TOTAL 16384
#define N_DIM   1024
#define K_DIM   1024
#define R_RANK  16

#define BM 64
#define BN 128
#define BK 64
#define NCHUNK (K_DIM / BK)   // 16
#define KSTEPS (BK / 16)      // 4

// stage: Xh 64x64 fp16 = 8KB, Wh 128x64 fp16 = 16KB (128B rows)
#define STG_XH 0
#define STG_WH 8192
#define STAGE_BYTES 24576
#define NSTAGE 3
#define SMEM_BYTES (NSTAGE * STAGE_BYTES)   // 72KB -> 3 CTAs/SM

#define XBLOCKS ((M_TOTAL * K_DIM) / (256 * 8))   // 8192

__device__ __half g_Xh[M_TOTAL * K_DIM];
__device__ __half g_Wh[N_DIM * K_DIM];

// ---------------- PTX helpers ----------------
__device__ __forceinline__ uint32_t smem_u32(const void* p) {
    uint32_t a;
    asm("{ .reg .u64 t; cvta.to.shared.u64 t, %1; cvt.u32.u64 %0, t; }" : "=r"(a) : "l"(p));
    return a;
}

#define CP_ASYNC16(dst, src) \
    asm volatile("cp.async.cg.shared.global [%0], [%1], 16;" :: "r"(dst), "l"(src))
#define CP_COMMIT() asm volatile("cp.async.commit_group;" ::: "memory")
#define CP_WAIT1()  asm volatile("cp.async.wait_group 1;" ::: "memory")
#define CP_WAIT0()  asm volatile("cp.async.wait_group 0;" ::: "memory")

#define LDSM_X4(r0, r1, r2, r3, addr) \
    asm volatile("ldmatrix.sync.aligned.m8n8.x4.shared.b16 {%0,%1,%2,%3}, [%4];" \
                 : "=r"(r0), "=r"(r1), "=r"(r2), "=r"(r3) : "r"(addr))

#define MMA_F16(d, a, b0, b1) \
    asm volatile("mma.sync.aligned.m16n8k16.row.col.f32.f16.f16.f32 " \
                 "{%0,%1,%2,%3}, {%4,%5,%6,%7}, {%8,%9}, {%0,%1,%2,%3};" \
                 : "+f"((d)[0]), "+f"((d)[1]), "+f"((d)[2]), "+f"((d)[3]) \
                 : "r"((a)[0]), "r"((a)[1]), "r"((a)[2]), "r"((a)[3]), \
                   "r"(b0), "r"(b1))

// pack fp16x2 {low=l, high=h}
__device__ __forceinline__ uint32_t pack_h2(float l, float h) {
    uint32_t r;
    asm("cvt.rn.f16x2.f32 %0, %1, %2;" : "=r"(r) : "f"(h), "f"(l));
    return r;
}

// ---------------------------------------------------------------------------
// Fused prep: blocks [0, XBLOCKS) convert X fp32->fp16;
//             blocks [XBLOCKS, XBLOCKS+N_DIM) build one W_eff row each.
// ---------------------------------------------------------------------------
__global__ __launch_bounds__(256) void prep_kernel(const float* __restrict__ X,
                                                   const float* __restrict__ W,
                                                   const float* __restrict__ A,
                                                   const float* __restrict__ Bm) {
    __shared__ float brow[R_RANK];
    const int t = threadIdx.x;

    if (blockIdx.x < XBLOCKS) {
        const size_t i8 = ((size_t)blockIdx.x * 256 + t) * 8;
        float4 v0 = *(const float4*)&X[i8];
        float4 v1 = *(const float4*)&X[i8 + 4];
        uint4 o;
        o.x = pack_h2(v0.x, v0.y);
        o.y = pack_h2(v0.z, v0.w);
        o.z = pack_h2(v1.x, v1.y);
        o.w = pack_h2(v1.z, v1.w);
        *(uint4*)&g_Xh[i8] = o;
    } else {
        const int o = blockIdx.x - XBLOCKS;
        if (t < R_RANK) brow[t] = 2.0f * Bm[o * R_RANK + t];
        __syncthreads();

        for (int k4 = t * 4; k4 < K_DIM; k4 += 256 * 4) {
            float4 w = *(const float4*)&W[o * K_DIM + k4];
            float v[4] = {w.x, w.y, w.z, w.w};
            #pragma unroll
            for (int r = 0; r < R_RANK; r++) {
                float br = brow[r];
                const float4 a = *(const float4*)&A[r * K_DIM + k4];
                v[0] = fmaf(br, a.x, v[0]); v[1] = fmaf(br, a.y, v[1]);
                v[2] = fmaf(br, a.z, v[2]); v[3] = fmaf(br, a.w, v[3]);
            }
            *(uint2*)&g_Wh[o * K_DIM + k4] =
                make_uint2(pack_h2(v[0], v[1]), pack_h2(v[2], v[3]));
        }
    }
}

// ---------------------------------------------------------------------------
// Main GEMM: 64x128 CTA, 256 threads (8 warps: 2M x 4N), warp tile 32x32.
// ---------------------------------------------------------------------------
__global__ __launch_bounds__(256, 3) void lora_gemm_f16_kernel(
    const float* __restrict__ bias,
    float* __restrict__ Out) {
    extern __shared__ char smem[];
    const uint32_t sbase = smem_u32(smem);
    const int tid = threadIdx.x;
    const int lane = tid & 31;
    const int wid = tid >> 5;          // 0..7
    const int wm = wid & 1;            // 2 warps along M (32 rows each)
    const int wn = wid >> 1;           // 4 warps along N (32 cols each)

    const int block_m = blockIdx.y * BM;
    const int block_n = blockIdx.x * BN;

    // ---- cp.async: X 512 chunks (2/thread), W 1024 chunks (4/thread).
    // cr = base row 0..31; i advances rows by 32 (swizzle-invariant).
    const int cr = tid >> 3;           // 0..31
    const int c8 = tid & 7;            // 16B chunk in 128B row
    const uint32_t dst_off = (uint32_t)(cr * 128 + ((c8 ^ (cr & 7)) << 4));
    const uint32_t dst_x = sbase + STG_XH + dst_off;
    const uint32_t dst_w = sbase + STG_WH + dst_off;
    const char* src_x = (const char*)(g_Xh + (size_t)(block_m + cr) * K_DIM + c8 * 8);
    const char* src_w = (const char*)(g_Wh + (size_t)(block_n + cr) * K_DIM + c8 * 8);
    // per i: dst += 4096B, src += 32*K_DIM*2 B; per chunk: src += BK*2 = 128B

    // ---- ldmatrix components (R16-verified) ----
    const int a_row = wm * 32 + (lane & 7) + ((lane >> 3) & 1) * 8;
    const uint32_t a_swz = (uint32_t)((a_row & 7) * 16);
    const int a_khalf = ((lane >> 4) & 1) * 16;
    const int b_rowl = (lane & 7) + ((lane >> 4) & 1) * 8;   // + wn*32 + np*16
    const int b_khalf = ((lane >> 3) & 1) * 16;

    float acc[2][4][4];
    #pragma unroll
    for (int mf = 0; mf < 2; mf++)
        #pragma unroll
        for (int nf = 0; nf < 4; nf++)
            #pragma unroll
            for (int r = 0; r < 4; r++)
                acc[mf][nf][r] = 0.0f;

    // prologue: stages 0, 1
    #pragma unroll
    for (int s = 0; s < 2; s++) {
        const uint32_t sb = (uint32_t)(s * STAGE_BYTES);
        const int ko = s * (BK * 2);
        #pragma unroll
        for (int i = 0; i < 2; i++)
            CP_ASYNC16(dst_x + sb + i * 4096, src_x + ko + i * (32 * K_DIM * 2));
        #pragma unroll
        for (int i = 0; i < 4; i++)
            CP_ASYNC16(dst_w + sb + i * 4096, src_w + ko + i * (32 * K_DIM * 2));
        CP_COMMIT();
    }

    for (int c = 0; c < NCHUNK; c++) {
        if (c + 1 < NCHUNK) CP_WAIT1(); else CP_WAIT0();
        __syncthreads();

        if (c + 2 < NCHUNK) {
            const uint32_t sb = (uint32_t)(((c + 2) % NSTAGE) * STAGE_BYTES);
            const int ko = (c + 2) * (BK * 2);
            #pragma unroll
            for (int i = 0; i < 2; i++)
                CP_ASYNC16(dst_x + sb + i * 4096, src_x + ko + i * (32 * K_DIM * 2));
            #pragma unroll
            for (int i = 0; i < 4; i++)
                CP_ASYNC16(dst_w + sb + i * 4096, src_w + ko + i * (32 * K_DIM * 2));
            CP_COMMIT();
        }

        const uint32_t buf = sbase + (uint32_t)((c % NSTAGE) * STAGE_BYTES);

        #pragma unroll
        for (int ks = 0; ks < KSTEPS; ks++) {
            uint32_t a[2][4], b[2][4];
            const uint32_t akb = (uint32_t)(ks * 32 + a_khalf) ^ a_swz;
            const uint32_t bkb = (uint32_t)(ks * 32 + b_khalf);
            // A: 2 m16-blocks of the 32-row warp tile
            #pragma unroll
            for (int mf = 0; mf < 2; mf++) {
                const uint32_t ao = (uint32_t)((a_row + mf * 16) * 128) + akb;
                LDSM_X4(a[mf][0], a[mf][1], a[mf][2], a[mf][3], buf + STG_XH + ao);
            }
            // B: 2 n16-blocks of the 32-col warp tile.
            // regs: r0=(n0-7,k0-7) r1=(n0-7,k8-15) r2=(n8-15,k0-7) r3=(n8-15,k8-15)
            #pragma unroll
            for (int np = 0; np < 2; np++) {
                const int row = wn * 32 + np * 16 + b_rowl;
                const uint32_t bo = (uint32_t)(row * 128) +
                                    (bkb ^ (uint32_t)((row & 7) * 16));
                LDSM_X4(b[np][0], b[np][1], b[np][2], b[np][3], buf + STG_WH + bo);
            }
            #pragma unroll
            for (int mf = 0; mf < 2; mf++)
                #pragma unroll
                for (int nf = 0; nf < 4; nf++) {
                    const int np = nf >> 1, h = nf & 1;
                    MMA_F16(acc[mf][nf], a[mf], b[np][2 * h], b[np][2 * h + 1]);
                }
        }
        // buffer reuse ordered by next iteration's wait + syncthreads
    }

    // ---- epilogue: bias + direct stores ----
    const int mrow = block_m + wm * 32 + (lane >> 2);
    const int ncol = block_n + wn * 32 + 2 * (lane & 3);
    #pragma unroll
    for (int mf = 0; mf < 2; mf++) {
        const int r0 = mrow + mf * 16;
        #pragma unroll
        for (int nf = 0; nf < 4; nf++) {
            const int n = ncol + nf * 8;
            const float2 bv = *(const float2*)&bias[n];
            float2 o0 = make_float2(acc[mf][nf][0] + bv.x, acc[mf][nf][1] + bv.y);
            float2 o1 = make_float2(acc[mf][nf][2] + bv.x, acc[mf][nf][3] + bv.y);
            *(float2*)&Out[(size_t)r0 * N_DIM + n] = o0;
            *(float2*)&Out[(size_t)(r0 + 8) * N_DIM + n] = o1;
        }
    }
}

// ---------------------------------------------------------------------------
extern "C" void kernel_launch(void* const* d_in, const int* in_sizes, int n_in,
                              void* d_out, int out_size) {
    const float* x  = (const float*)d_in[0];
    const float* W  = (const float*)d_in[1];
    const float* b  = (const float*)d_in[2];
    const float* A  = (const float*)d_in[3];
    const float* Bm = (const float*)d_in[4];
    float* out = (float*)d_out;

    cudaFuncSetAttribute(lora_gemm_f16_kernel,
                         cudaFuncAttributeMaxDynamicSharedMemorySize, SMEM_BYTES);

    prep_kernel<<<XBLOCKS + N_DIM, 256>>>(x, W, A, Bm);

    dim3 grid(N_DIM / BN, M_TOTAL / BM);   // (8, 256) = 2048 CTAs
    lora_gemm_f16_kernel<<<grid, 256, SMEM_BYTES>>>(b, out);
}